// round 1
// baseline (speedup 1.0000x reference)
#include <cuda_runtime.h>

#define NQ 12
#define NSTATE (1 << NQ)     // 4096
#define NPAIR (NSTATE / 2)   // 2048
#define NTHREADS 256
#define NL 2

__device__ __forceinline__ int insert_zero(int v, int pos) {
    int mask = (1 << pos) - 1;
    return ((v & ~mask) << 1) | (v & mask);
}

// One CTA per batch element. State (re/im split) lives in shared memory.
// Reference bit convention: qubit j <-> bit (NQ-1-j) of the flat state index.
__global__ void __launch_bounds__(NTHREADS, 1)
qsim_kernel(const float* __restrict__ x, const float* __restrict__ w,
            float* __restrict__ out) {
    __shared__ float s_re[NSTATE];
    __shared__ float s_im[NSTATE];
    __shared__ float g_c[NL][NQ];   // per-layer RX trig, indexed by BIT
    __shared__ float g_s[NL][NQ];
    __shared__ float i_c[NQ];       // input-layer trig, indexed by BIT
    __shared__ float i_s[NQ];
    __shared__ float w_acc[NTHREADS / 32][NQ];

    const int tid = threadIdx.x;
    const int blk = blockIdx.x;

    // ---- precompute trig (bit q corresponds to qubit NQ-1-q) ----
    if (tid < NQ) {
        float th = 0.5f * x[blk * NQ + (NQ - 1 - tid)];
        i_c[tid] = cosf(th);
        i_s[tid] = sinf(th);
    } else if (tid < NQ + NL * NQ) {
        int t = tid - NQ;
        int l = t / NQ, q = t % NQ;
        float th = 0.5f * w[l * NQ + (NQ - 1 - q)];
        g_c[l][q] = cosf(th);
        g_s[l][q] = sinf(th);
    }
    __syncthreads();

    // ---- product-state init: first RX layer applied to |0...0> ----
    // amp(i) = (-i)^popcount(i) * prod_b (bit_b(i) ? sin_b : cos_b)
    {
        float mh = 1.0f;
        #pragma unroll
        for (int bb = 0; bb < 8; bb++)
            mh *= ((tid >> bb) & 1) ? i_s[bb + 4] : i_c[bb + 4];
        int pch = __popc(tid);
        #pragma unroll
        for (int r = 0; r < 16; r++) {
            float m = mh;
            #pragma unroll
            for (int bb = 0; bb < 4; bb++)
                m *= ((r >> bb) & 1) ? i_s[bb] : i_c[bb];
            int pc = (pch + __popc(r)) & 3;
            int i = tid * 16 + r;
            float re = 0.f, im = 0.f;
            if (pc == 0)      re = m;
            else if (pc == 1) im = -m;
            else if (pc == 2) re = -m;
            else              im = m;
            s_re[i] = re;
            s_im[i] = im;
        }
    }
    __syncthreads();

    // ---- variational layers ----
    #pragma unroll 1
    for (int l = 0; l < NL; l++) {
        // RX on every qubit (single-qubit gates on distinct qubits commute;
        // iterate by bit position directly).
        #pragma unroll 1
        for (int q = 0; q < NQ; q++) {
            float c = g_c[l][q];
            float s = g_s[l][q];
            #pragma unroll
            for (int it = 0; it < NPAIR / NTHREADS; it++) {
                int k  = tid + it * NTHREADS;
                int i0 = insert_zero(k, q);
                int i1 = i0 | (1 << q);
                float are = s_re[i0], aim = s_im[i0];
                float bre = s_re[i1], bim = s_im[i1];
                // RX: new0 = c*s0 - i*s*s1 ; new1 = -i*s*s0 + c*s1
                s_re[i0] = fmaf(c, are,  s * bim);
                s_im[i0] = fmaf(c, aim, -s * bre);
                s_re[i1] = fmaf(c, bre,  s * aim);
                s_im[i1] = fmaf(c, bim, -s * are);
            }
            __syncthreads();
        }
        // CNOT ring: gate j has ctrl qubit j, tgt qubit (j+1)%NQ. Order matters.
        #pragma unroll 1
        for (int j = 0; j < NQ; j++) {
            int cb = NQ - 1 - j;                          // ctrl bit
            int tb = (j < NQ - 1) ? (NQ - 2 - j) : (NQ - 1); // tgt bit
            int a  = cb < tb ? cb : tb;
            int bb = cb < tb ? tb : cb;
            #pragma unroll
            for (int it = 0; it < (NSTATE / 4) / NTHREADS; it++) {
                int k  = tid + it * NTHREADS;
                int t1 = insert_zero(k, a);
                int i  = insert_zero(t1, bb);
                int i0 = i | (1 << cb);       // ctrl=1, tgt=0
                int i1 = i0 | (1 << tb);      // ctrl=1, tgt=1
                float r0 = s_re[i0], m0 = s_im[i0];
                float r1 = s_re[i1], m1 = s_im[i1];
                s_re[i0] = r1; s_im[i0] = m1;
                s_re[i1] = r0; s_im[i1] = m0;
            }
            __syncthreads();
        }
    }

    // ---- expectations: <Z_q> over bit q, output index i uses bit (NQ-1-i) ----
    float acc[NQ];
    #pragma unroll
    for (int q = 0; q < NQ; q++) acc[q] = 0.f;
    #pragma unroll
    for (int r = 0; r < 16; r++) {
        int i = tid * 16 + r;
        float re = s_re[i], im = s_im[i];
        float p = fmaf(re, re, im * im);
        #pragma unroll
        for (int q = 0; q < NQ; q++)
            acc[q] += ((i >> q) & 1) ? -p : p;
    }
    // deterministic reduction: warp shfl -> smem -> ordered sum
    #pragma unroll
    for (int q = 0; q < NQ; q++) {
        float v = acc[q];
        #pragma unroll
        for (int off = 16; off; off >>= 1)
            v += __shfl_xor_sync(0xffffffffu, v, off);
        acc[q] = v;
    }
    if ((tid & 31) == 0) {
        int wdi = tid >> 5;
        #pragma unroll
        for (int q = 0; q < NQ; q++) w_acc[wdi][q] = acc[q];
    }
    __syncthreads();
    if (tid < NQ) {
        float v = 0.f;
        #pragma unroll
        for (int wi = 0; wi < NTHREADS / 32; wi++) v += w_acc[wi][tid];
        out[blk * NQ + (NQ - 1 - tid)] = v;
    }
}

extern "C" void kernel_launch(void* const* d_in, const int* in_sizes, int n_in,
                              void* d_out, int out_size) {
    const float* x = (const float*)d_in[0];   // (B, 12) float32
    const float* w = (const float*)d_in[1];   // (2, 12) float32
    float* out = (float*)d_out;               // (B, 12) float32
    int B = in_sizes[0] / NQ;
    qsim_kernel<<<B, NTHREADS>>>(x, w, out);
}

// round 2
// speedup vs baseline: 3.3282x; 3.3282x over previous
#include <cuda_runtime.h>

#define NQ 12
#define NSTATE 4096
#define NT 256
#define NL 2

// Amplitude index i = tid*16 + r :
//   bits 0-3  = register index r
//   bits 4-8  = lane (tid & 31)
//   bits 9-11 = warp (tid >> 5)
// Reference bit convention: qubit j <-> bit (11-j) of the flat state index.

template<int B>
__device__ __forceinline__ void rx_local(float (&re)[16], float (&im)[16], float c, float s) {
    #pragma unroll
    for (int r = 0; r < 16; r++) {
        if (!((r >> B) & 1)) {
            const int r1 = r | (1 << B);
            float are = re[r], aim = im[r], bre = re[r1], bim = im[r1];
            re[r]  = fmaf(c, are,  s * bim);
            im[r]  = fmaf(c, aim, -s * bre);
            re[r1] = fmaf(c, bre,  s * aim);
            im[r1] = fmaf(c, bim, -s * are);
        }
    }
}

// RX across a lane bit: symmetric on both sides of the pair.
__device__ __forceinline__ void rx_lane(float (&re)[16], float (&im)[16], int m, float c, float s) {
    #pragma unroll
    for (int r = 0; r < 16; r++) {
        float pre = __shfl_xor_sync(0xffffffffu, re[r], m);
        float pim = __shfl_xor_sync(0xffffffffu, im[r], m);
        re[r] = fmaf(c, re[r],  s * pim);
        im[r] = fmaf(c, im[r], -s * pre);
    }
}

template<int CB, int TB>
__device__ __forceinline__ void cnot_local(float (&re)[16], float (&im)[16]) {
    #pragma unroll
    for (int r = 0; r < 16; r++) {
        if (((r >> CB) & 1) && !((r >> TB) & 1)) {
            const int r1 = r ^ (1 << TB);
            float t;
            t = re[r]; re[r] = re[r1]; re[r1] = t;
            t = im[r]; im[r] = im[r1]; im[r1] = t;
        }
    }
}

// CNOT with ctrl and tgt both on lane bits: lane permutation via index shuffle.
__device__ __forceinline__ void cnot_lane(float (&re)[16], float (&im)[16], int lane, int cm, int tm) {
    const int src = (lane & cm) ? (lane ^ tm) : lane;
    #pragma unroll
    for (int r = 0; r < 16; r++) {
        re[r] = __shfl_sync(0xffffffffu, re[r], src);
        im[r] = __shfl_sync(0xffffffffu, im[r], src);
    }
}

__global__ void __launch_bounds__(NT, 3)
qsim_kernel(const float* __restrict__ x, const float* __restrict__ w,
            float* __restrict__ out) {
    __shared__ float sbuf_re[NSTATE];
    __shared__ float sbuf_im[NSTATE];
    __shared__ float tc[NL + 1][NQ];   // trig, indexed by logical BIT
    __shared__ float tsn[NL + 1][NQ];
    __shared__ float w_acc[NT / 32][NQ];

    const int tid  = threadIdx.x;
    const int lane = tid & 31;
    const int warp = tid >> 5;
    const int blk  = blockIdx.x;

    // trig: logical bit q corresponds to qubit (11-q)
    if (tid < NQ) {
        float th = 0.5f * x[blk * NQ + (NQ - 1 - tid)];
        tc[0][tid] = cosf(th);
        tsn[0][tid] = sinf(th);
    } else if (tid < NQ * (NL + 1)) {
        int t = tid - NQ;
        int l = t / NQ, q = t % NQ;
        float th = 0.5f * w[l * NQ + (NQ - 1 - q)];
        tc[l + 1][q] = cosf(th);
        tsn[l + 1][q] = sinf(th);
    }
    __syncthreads();

    float re[16], im[16];

    // ---- init: product state after first RX layer on |0...0> ----
    // amp(i) = (-i)^popcount(i) * prod_b (bit_b ? sin_b : cos_b)
    {
        float mh = 1.0f;
        #pragma unroll
        for (int b = 0; b < 8; b++)
            mh *= ((tid >> b) & 1) ? tsn[0][b + 4] : tc[0][b + 4];
        int pch = __popc(tid);
        #pragma unroll
        for (int r = 0; r < 16; r++) {
            float m = mh;
            #pragma unroll
            for (int b = 0; b < 4; b++)
                m *= ((r >> b) & 1) ? tsn[0][b] : tc[0][b];
            int pc = (pch + __popc(r)) & 3;
            re[r] = (pc == 0) ? m : (pc == 2) ? -m : 0.0f;
            im[r] = (pc == 1) ? -m : (pc == 3) ? m : 0.0f;
        }
    }

    // ---- variational layers (frame is identity at each layer start) ----
    #pragma unroll 1
    for (int l = 1; l <= NL; l++) {
        // RX logical bits 0..3 (register bits)
        rx_local<0>(re, im, tc[l][0], tsn[l][0]);
        rx_local<1>(re, im, tc[l][1], tsn[l][1]);
        rx_local<2>(re, im, tc[l][2], tsn[l][2]);
        rx_local<3>(re, im, tc[l][3], tsn[l][3]);
        // RX logical bits 4..8 (lane bits 0..4)
        rx_lane(re, im, 1,  tc[l][4], tsn[l][4]);
        rx_lane(re, im, 2,  tc[l][5], tsn[l][5]);
        rx_lane(re, im, 4,  tc[l][6], tsn[l][6]);
        rx_lane(re, im, 8,  tc[l][7], tsn[l][7]);
        rx_lane(re, im, 16, tc[l][8], tsn[l][8]);

        // ---- Swap A: exchange bit groups 0-2 <-> 9-11 (conflict-free) ----
        __syncthreads();   // guard: prior readers of sbuf done
        #pragma unroll
        for (int r = 0; r < 16; r++) {
            sbuf_re[r * 256 + tid] = re[r];
            sbuf_im[r * 256 + tid] = im[r];
        }
        __syncthreads();
        #pragma unroll
        for (int r = 0; r < 16; r++) {
            // src = sigma(i):  row = src&15, col = src>>4
            int row = (warp & 7) | (r & 8);
            int col = lane | ((r & 7) << 5);
            re[r] = sbuf_re[row * 256 + col];
            im[r] = sbuf_im[row * 256 + col];
        }
        // frame: logical 9,10,11 now at slot bits 0,1,2; logical 0,1,2 at warp bits

        // RX logical 9,10,11
        rx_local<0>(re, im, tc[l][9],  tsn[l][9]);
        rx_local<1>(re, im, tc[l][10], tsn[l][10]);
        rx_local<2>(re, im, tc[l][11], tsn[l][11]);

        // CNOT(11,10) = slots (2,1); CNOT(10,9) = slots (1,0)
        cnot_local<2, 1>(re, im);
        cnot_local<1, 0>(re, im);

        // CNOT(9,8): ctrl slot bit0 (register), tgt slot bit8 (lane mask 16)
        #pragma unroll
        for (int r = 1; r < 16; r += 2) {
            re[r] = __shfl_xor_sync(0xffffffffu, re[r], 16);
            im[r] = __shfl_xor_sync(0xffffffffu, im[r], 16);
        }
        // CNOT(8,7),(7,6),(6,5),(5,4): lane-lane
        cnot_lane(re, im, lane, 16, 8);
        cnot_lane(re, im, lane, 8,  4);
        cnot_lane(re, im, lane, 4,  2);
        cnot_lane(re, im, lane, 2,  1);
        // CNOT(4,3): ctrl lane bit0, tgt slot bit3 (register swap when ctrl=1)
        if (lane & 1) {
            #pragma unroll
            for (int r = 0; r < 8; r++) {
                float t;
                t = re[r]; re[r] = re[r + 8]; re[r + 8] = t;
                t = im[r]; im[r] = im[r + 8]; im[r + 8] = t;
            }
        }

        // ---- Swap B fused with CNOT(3,2),(2,1),(1,0),(0,11) ----
        // F[i] = A[sigma(j)],  j = c32(c21(c10(c011(i))))  (c011 applied first)
        __syncthreads();   // guard vs swap-A readers
        #pragma unroll
        for (int r = 0; r < 16; r++) {
            sbuf_re[r * 256 + tid] = re[r];
            sbuf_im[r * 256 + tid] = im[r];
        }
        __syncthreads();
        #pragma unroll
        for (int r = 0; r < 16; r++) {
            int rp = r ^ ((r >> 1) & 1);          // c10 : flip bit0 if bit1
            rp ^= ((rp >> 2) & 1) << 1;           // c21 : flip bit1 if bit2
            rp ^= ((rp >> 3) & 1) << 2;           // c32 : flip bit2 if bit3
            int wx = warp ^ ((r & 1) << 2);       // c011: flip bit11 if bit0
            int row = (wx & 7) | (rp & 8);        // sigma(j) & 15
            int col = lane | ((rp & 7) << 5);     // sigma(j) >> 4
            re[r] = sbuf_re[row * 256 + col];
            im[r] = sbuf_im[row * 256 + col];
        }
        // frame back to identity; layer complete
    }

    // ---- expectations: <Z over bit q>, i = tid*16 + r ----
    float ptot = 0.0f;
    float s03[4] = {0.0f, 0.0f, 0.0f, 0.0f};
    #pragma unroll
    for (int r = 0; r < 16; r++) {
        float p = fmaf(re[r], re[r], im[r] * im[r]);
        ptot += p;
        #pragma unroll
        for (int q = 0; q < 4; q++)
            s03[q] += ((r >> q) & 1) ? -p : p;
    }
    float acc[NQ];
    #pragma unroll
    for (int q = 0; q < 4; q++) acc[q] = s03[q];
    #pragma unroll
    for (int q = 4; q < NQ; q++)
        acc[q] = ((tid >> (q - 4)) & 1) ? -ptot : ptot;

    #pragma unroll
    for (int q = 0; q < NQ; q++) {
        float v = acc[q];
        #pragma unroll
        for (int off = 16; off; off >>= 1)
            v += __shfl_xor_sync(0xffffffffu, v, off);
        acc[q] = v;
    }
    if (lane == 0) {
        #pragma unroll
        for (int q = 0; q < NQ; q++) w_acc[warp][q] = acc[q];
    }
    __syncthreads();
    if (tid < NQ) {
        float v = 0.0f;
        #pragma unroll
        for (int wi = 0; wi < NT / 32; wi++) v += w_acc[wi][tid];
        out[blk * NQ + (NQ - 1 - tid)] = v;
    }
}

extern "C" void kernel_launch(void* const* d_in, const int* in_sizes, int n_in,
                              void* d_out, int out_size) {
    const float* x = (const float*)d_in[0];   // (B, 12) float32
    const float* w = (const float*)d_in[1];   // (2, 12) float32
    float* out = (float*)d_out;               // (B, 12) float32
    int B = in_sizes[0] / NQ;
    qsim_kernel<<<B, NT>>>(x, w, out);
}

// round 3
// speedup vs baseline: 4.3113x; 1.2954x over previous
#include <cuda_runtime.h>

#define NQ 12
#define NT 256
#define NL 2

// Amplitude index i = tid*16 + r :
//   bits 0-3 = register r, bits 4-8 = lane, bits 9-11 = warp.
// Reference convention: qubit j <-> bit (11-j) of the flat state index.

template<int B>
__device__ __forceinline__ void rx_local(float2 (&a)[16], float c, float s) {
    #pragma unroll
    for (int r = 0; r < 16; r++) {
        if (!((r >> B) & 1)) {
            const int r1 = r | (1 << B);
            float x0 = a[r].x, y0 = a[r].y, x1 = a[r1].x, y1 = a[r1].y;
            a[r].x  = fmaf(c, x0,  s * y1);
            a[r].y  = fmaf(c, y0, -s * x1);
            a[r1].x = fmaf(c, x1,  s * y0);
            a[r1].y = fmaf(c, y1, -s * x0);
        }
    }
}

__device__ __forceinline__ void rx_lane(float2 (&a)[16], int m, float c, float s) {
    #pragma unroll
    for (int r = 0; r < 16; r++) {
        float px = __shfl_xor_sync(0xffffffffu, a[r].x, m);
        float py = __shfl_xor_sync(0xffffffffu, a[r].y, m);
        a[r].x = fmaf(c, a[r].x,  s * py);
        a[r].y = fmaf(c, a[r].y, -s * px);
    }
}

template<int CB, int TB>
__device__ __forceinline__ void cnot_local(float2 (&a)[16]) {
    #pragma unroll
    for (int r = 0; r < 16; r++) {
        if (((r >> CB) & 1) && !((r >> TB) & 1)) {
            const int r1 = r ^ (1 << TB);
            float2 t = a[r]; a[r] = a[r1]; a[r1] = t;
        }
    }
}

__global__ void __launch_bounds__(NT, 3)
qsim_kernel(const float* __restrict__ x, const float* __restrict__ w,
            float* __restrict__ out) {
    __shared__ float2 sbuf[4096];          // 32 KB state buffer (re,im pairs)
    __shared__ float tc[NL + 1][NQ];       // trig, indexed by logical BIT
    __shared__ float tsn[NL + 1][NQ];
    __shared__ float w_acc[NT / 32][NQ];

    const int tid  = threadIdx.x;
    const int lane = tid & 31;
    const int warp = tid >> 5;
    const int blk  = blockIdx.x;

    if (tid < NQ) {
        float th = 0.5f * x[blk * NQ + (NQ - 1 - tid)];
        tc[0][tid] = cosf(th);
        tsn[0][tid] = sinf(th);
    } else if (tid < NQ * (NL + 1)) {
        int t = tid - NQ;
        int l = t / NQ, q = t % NQ;
        float th = 0.5f * w[l * NQ + (NQ - 1 - q)];
        tc[l + 1][q] = cosf(th);
        tsn[l + 1][q] = sinf(th);
    }
    __syncthreads();

    float2 a[16];

    // ---- init: product state after first RX layer on |0...0> ----
    {
        float mh = 1.0f;
        #pragma unroll
        for (int b = 0; b < 8; b++)
            mh *= ((tid >> b) & 1) ? tsn[0][b + 4] : tc[0][b + 4];
        int pch = __popc(tid);
        #pragma unroll
        for (int r = 0; r < 16; r++) {
            float m = mh;
            #pragma unroll
            for (int b = 0; b < 4; b++)
                m *= ((r >> b) & 1) ? tsn[0][b] : tc[0][b];
            int pc = (pch + __popc(r)) & 3;
            a[r].x = (pc == 0) ? m : (pc == 2) ? -m : 0.0f;
            a[r].y = (pc == 1) ? -m : (pc == 3) ? m : 0.0f;
        }
    }

    // precompute merged lane-CNOT source (same both layers):
    // composition of C(8,7),C(7,6),C(6,5),C(5,4) lane perms (C(9,8) folded per-reg)
    int s0 = lane;
    s0 ^= (s0 >> 1) & 1;
    s0 ^= ((s0 >> 2) & 1) << 1;
    s0 ^= ((s0 >> 3) & 1) << 2;
    s0 ^= ((s0 >> 4) & 1) << 3;
    const int s1 = s0 ^ 16;

    #pragma unroll 1
    for (int l = 1; l <= NL; l++) {
        // RX logical bits 0..3 (register bits)
        rx_local<0>(a, tc[l][0], tsn[l][0]);
        rx_local<1>(a, tc[l][1], tsn[l][1]);
        rx_local<2>(a, tc[l][2], tsn[l][2]);
        rx_local<3>(a, tc[l][3], tsn[l][3]);
        // RX logical bits 4..8 (lane bits)
        rx_lane(a, 1,  tc[l][4], tsn[l][4]);
        rx_lane(a, 2,  tc[l][5], tsn[l][5]);
        rx_lane(a, 4,  tc[l][6], tsn[l][6]);
        rx_lane(a, 8,  tc[l][7], tsn[l][7]);
        rx_lane(a, 16, tc[l][8], tsn[l][8]);

        // ---- Swap A: exchange slot bits 0-2 <-> 9-11 ----
        if (l == 2) __syncthreads();           // guard vs layer-1 SwapB readers
        #pragma unroll
        for (int r = 0; r < 16; r++)
            sbuf[r * 256 + tid] = a[r];
        __syncthreads();
        #pragma unroll
        for (int r = 0; r < 16; r++) {
            int row = (warp & 7) | (r & 8);
            int col = lane | ((r & 7) << 5);
            a[r] = sbuf[row * 256 + col];
        }
        // frame A: slots 0,1,2 = logical 9,10,11; slot3 = 3; lanes = 4-8; W = 0,1,2

        // RX logical 9,10,11
        rx_local<0>(a, tc[l][9],  tsn[l][9]);
        rx_local<1>(a, tc[l][10], tsn[l][10]);
        rx_local<2>(a, tc[l][11], tsn[l][11]);

        // CNOT(11,10), CNOT(10,9): register renames
        cnot_local<2, 1>(a);
        cnot_local<1, 0>(a);

        // Merged CNOT(9,8) + CNOT(8,7),(7,6),(6,5),(5,4): one shfl pass
        #pragma unroll
        for (int r = 0; r < 16; r++) {
            const int src = (r & 1) ? s1 : s0;
            a[r].x = __shfl_sync(0xffffffffu, a[r].x, src);
            a[r].y = __shfl_sync(0xffffffffu, a[r].y, src);
        }
        // CNOT(4,3): ctrl lane bit0, tgt slot bit3
        {
            const bool p = (lane & 1) != 0;
            #pragma unroll
            for (int r = 0; r < 8; r++) {
                float2 lo = a[r], hi = a[r + 8];
                a[r]     = p ? hi : lo;
                a[r + 8] = p ? lo : hi;
            }
        }

        if (l == 1) {
            // ---- Swap B fused with CNOT(3,2),(2,1),(1,0),(0,11): back to identity ----
            __syncthreads();                   // guard vs SwapA readers
            #pragma unroll
            for (int r = 0; r < 16; r++)
                sbuf[r * 256 + tid] = a[r];
            __syncthreads();
            #pragma unroll
            for (int r = 0; r < 16; r++) {
                int rp = r ^ ((r >> 1) & 1);
                rp ^= ((rp >> 2) & 1) << 1;
                rp ^= ((rp >> 3) & 1) << 2;
                int wx = warp ^ ((r & 1) << 2);
                int row = (wx & 7) | (rp & 8);
                int col = lane | ((rp & 7) << 5);
                a[r] = sbuf[row * 256 + col];
            }
        }
        // l==2: stay in frame A with pending perm Q; folded into expectations below
    }

    // ---- expectations with frame+perm fold ----
    // Slot (warp,lane,r) holds true amplitude of logical index v where:
    //   rp = warp | (r&8);  R = F^{-1}(rp);  W = (r&7) ^ ((R&1)<<2)
    //   v bits: 0-3 = R, 4-8 = lane, 9-11 = W.
    // F^{-1}: r3=rp3; r2=rp2^r3; r1=rp1^r2; r0=rp0^r1.  R_hi = R_lo ^ 15.
    int r2b = (warp >> 2) & 1;
    int r1b = ((warp >> 1) & 1) ^ r2b;
    int r0b = (warp & 1) ^ r1b;
    const int Rlo = r0b | (r1b << 1) | (r2b << 2);   // bit3 = 0

    float p_lo = 0.f, p_hi = 0.f, acc9 = 0.f, acc10 = 0.f, acc11 = 0.f;
    #pragma unroll
    for (int r = 0; r < 16; r++) {
        float p = fmaf(a[r].x, a[r].x, a[r].y * a[r].y);
        if (r < 8) p_lo += p; else p_hi += p;
        acc9  += (r & 1) ? -p : p;
        acc10 += (r & 2) ? -p : p;
        int sb = ((r >> 2) ^ (r >> 3) ^ Rlo) & 1;     // v11 sign bit
        acc11 += sb ? -p : p;
    }
    const float ptot = p_lo + p_hi;
    const float dlh  = p_lo - p_hi;

    float acc[NQ];
    #pragma unroll
    for (int q = 0; q < 4; q++)
        acc[q] = ((Rlo >> q) & 1) ? -dlh : dlh;
    #pragma unroll
    for (int q = 4; q < 9; q++)
        acc[q] = ((lane >> (q - 4)) & 1) ? -ptot : ptot;
    acc[9] = acc9; acc[10] = acc10; acc[11] = acc11;

    #pragma unroll
    for (int q = 0; q < NQ; q++) {
        float v = acc[q];
        #pragma unroll
        for (int off = 16; off; off >>= 1)
            v += __shfl_xor_sync(0xffffffffu, v, off);
        acc[q] = v;
    }
    if (lane == 0) {
        #pragma unroll
        for (int q = 0; q < NQ; q++) w_acc[warp][q] = acc[q];
    }
    __syncthreads();
    if (tid < NQ) {
        float v = 0.0f;
        #pragma unroll
        for (int wi = 0; wi < NT / 32; wi++) v += w_acc[wi][tid];
        out[blk * NQ + (NQ - 1 - tid)] = v;
    }
}

extern "C" void kernel_launch(void* const* d_in, const int* in_sizes, int n_in,
                              void* d_out, int out_size) {
    const float* x = (const float*)d_in[0];   // (B, 12) float32
    const float* w = (const float*)d_in[1];   // (2, 12) float32
    float* out = (float*)d_out;               // (B, 12) float32
    int B = in_sizes[0] / NQ;
    qsim_kernel<<<B, NT>>>(x, w, out);
}

// round 4
// speedup vs baseline: 4.3342x; 1.0053x over previous
#include <cuda_runtime.h>

#define NQ 12
#define NT 256
#define NL 2

// Amplitude index i = tid*16 + r :
//   bits 0-3 = register r, bits 4-8 = lane, bits 9-11 = warp.
// Reference convention: qubit j <-> bit (11-j) of the flat state index.

template<int B>
__device__ __forceinline__ void rx_local(float2 (&a)[16], float c, float s) {
    #pragma unroll
    for (int r = 0; r < 16; r++) {
        if (!((r >> B) & 1)) {
            const int r1 = r | (1 << B);
            float x0 = a[r].x, y0 = a[r].y, x1 = a[r1].x, y1 = a[r1].y;
            a[r].x  = fmaf(c, x0,  s * y1);
            a[r].y  = fmaf(c, y0, -s * x1);
            a[r1].x = fmaf(c, x1,  s * y0);
            a[r1].y = fmaf(c, y1, -s * x0);
        }
    }
}

__device__ __forceinline__ void rx_lane(float2 (&a)[16], int m, float c, float s) {
    #pragma unroll
    for (int r = 0; r < 16; r++) {
        float px = __shfl_xor_sync(0xffffffffu, a[r].x, m);
        float py = __shfl_xor_sync(0xffffffffu, a[r].y, m);
        a[r].x = fmaf(c, a[r].x,  s * py);
        a[r].y = fmaf(c, a[r].y, -s * px);
    }
}

template<int CB, int TB>
__device__ __forceinline__ void cnot_local(float2 (&a)[16]) {
    #pragma unroll
    for (int r = 0; r < 16; r++) {
        if (((r >> CB) & 1) && !((r >> TB) & 1)) {
            const int r1 = r ^ (1 << TB);
            float2 t = a[r]; a[r] = a[r1]; a[r1] = t;
        }
    }
}

__global__ void __launch_bounds__(NT, 3)
qsim_kernel(const float* __restrict__ x, const float* __restrict__ w,
            float* __restrict__ out) {
    __shared__ float2 sbuf[4096];          // 32 KB state buffer (re,im pairs)
    __shared__ float tc[NL + 1][NQ];       // trig, indexed by logical BIT
    __shared__ float tsn[NL + 1][NQ];
    __shared__ float w_acc[NT / 32][NQ];

    const int tid  = threadIdx.x;
    const int lane = tid & 31;
    const int warp = tid >> 5;
    const int blk  = blockIdx.x;

    if (tid < NQ) {
        float th = 0.5f * x[blk * NQ + (NQ - 1 - tid)];
        tc[0][tid] = cosf(th);
        tsn[0][tid] = sinf(th);
    } else if (tid < NQ * (NL + 1)) {
        int t = tid - NQ;
        int l = t / NQ, q = t % NQ;
        float th = 0.5f * w[l * NQ + (NQ - 1 - q)];
        tc[l + 1][q] = cosf(th);
        tsn[l + 1][q] = sinf(th);
    }
    __syncthreads();

    float2 a[16];

    // ---- init: product state after first RX layer on |0...0> ----
    {
        float mh = 1.0f;
        #pragma unroll
        for (int b = 0; b < 8; b++)
            mh *= ((tid >> b) & 1) ? tsn[0][b + 4] : tc[0][b + 4];
        int pch = __popc(tid);
        #pragma unroll
        for (int r = 0; r < 16; r++) {
            float m = mh;
            #pragma unroll
            for (int b = 0; b < 4; b++)
                m *= ((r >> b) & 1) ? tsn[0][b] : tc[0][b];
            int pc = (pch + __popc(r)) & 3;
            a[r].x = (pc == 0) ? m : (pc == 2) ? -m : 0.0f;
            a[r].y = (pc == 1) ? -m : (pc == 3) ? m : 0.0f;
        }
    }

    // precompute merged lane-CNOT source (same both layers):
    // composition of C(8,7),C(7,6),C(6,5),C(5,4) lane perms (C(9,8) folded per-reg)
    int s0 = lane;
    s0 ^= (s0 >> 1) & 1;
    s0 ^= ((s0 >> 2) & 1) << 1;
    s0 ^= ((s0 >> 3) & 1) << 2;
    s0 ^= ((s0 >> 4) & 1) << 3;
    const int s1 = s0 ^ 16;

    #pragma unroll 1
    for (int l = 1; l <= NL; l++) {
        // RX logical bits 0..3 (register bits)
        rx_local<0>(a, tc[l][0], tsn[l][0]);
        rx_local<1>(a, tc[l][1], tsn[l][1]);
        rx_local<2>(a, tc[l][2], tsn[l][2]);
        rx_local<3>(a, tc[l][3], tsn[l][3]);
        // RX logical bits 4..8 (lane bits)
        rx_lane(a, 1,  tc[l][4], tsn[l][4]);
        rx_lane(a, 2,  tc[l][5], tsn[l][5]);
        rx_lane(a, 4,  tc[l][6], tsn[l][6]);
        rx_lane(a, 8,  tc[l][7], tsn[l][7]);
        rx_lane(a, 16, tc[l][8], tsn[l][8]);

        // ---- Swap A: exchange slot bits 0-2 <-> 9-11 ----
        if (l == 2) __syncthreads();           // guard vs layer-1 SwapB readers
        #pragma unroll
        for (int r = 0; r < 16; r++)
            sbuf[r * 256 + tid] = a[r];
        __syncthreads();
        #pragma unroll
        for (int r = 0; r < 16; r++) {
            int row = (warp & 7) | (r & 8);
            int col = lane | ((r & 7) << 5);
            a[r] = sbuf[row * 256 + col];
        }
        // frame A: slots 0,1,2 = logical 9,10,11; slot3 = 3; lanes = 4-8; W = 0,1,2

        // RX logical 9,10,11
        rx_local<0>(a, tc[l][9],  tsn[l][9]);
        rx_local<1>(a, tc[l][10], tsn[l][10]);
        rx_local<2>(a, tc[l][11], tsn[l][11]);

        // CNOT(11,10), CNOT(10,9): register renames
        cnot_local<2, 1>(a);
        cnot_local<1, 0>(a);

        // Merged CNOT(9,8) + CNOT(8,7),(7,6),(6,5),(5,4): one shfl pass
        #pragma unroll
        for (int r = 0; r < 16; r++) {
            const int src = (r & 1) ? s1 : s0;
            a[r].x = __shfl_sync(0xffffffffu, a[r].x, src);
            a[r].y = __shfl_sync(0xffffffffu, a[r].y, src);
        }
        // CNOT(4,3): ctrl lane bit0, tgt slot bit3
        {
            const bool p = (lane & 1) != 0;
            #pragma unroll
            for (int r = 0; r < 8; r++) {
                float2 lo = a[r], hi = a[r + 8];
                a[r]     = p ? hi : lo;
                a[r + 8] = p ? lo : hi;
            }
        }

        if (l == 1) {
            // ---- Swap B fused with CNOT(3,2),(2,1),(1,0),(0,11): back to identity ----
            __syncthreads();                   // guard vs SwapA readers
            #pragma unroll
            for (int r = 0; r < 16; r++)
                sbuf[r * 256 + tid] = a[r];
            __syncthreads();
            #pragma unroll
            for (int r = 0; r < 16; r++) {
                int rp = r ^ ((r >> 1) & 1);
                rp ^= ((rp >> 2) & 1) << 1;
                rp ^= ((rp >> 3) & 1) << 2;
                int wx = warp ^ ((r & 1) << 2);
                int row = (wx & 7) | (rp & 8);
                int col = lane | ((rp & 7) << 5);
                a[r] = sbuf[row * 256 + col];
            }
        }
        // l==2: stay in frame A with pending perm Q; folded into expectations below
    }

    // ---- expectations with frame+perm fold ----
    // Slot (warp,lane,r) holds true amplitude of logical index v where:
    //   rp = warp | (r&8);  R = F^{-1}(rp);  W = (r&7) ^ ((R&1)<<2)
    //   v bits: 0-3 = R, 4-8 = lane, 9-11 = W.
    // F^{-1}: r3=rp3; r2=rp2^r3; r1=rp1^r2; r0=rp0^r1.  R_hi = R_lo ^ 15.
    int r2b = (warp >> 2) & 1;
    int r1b = ((warp >> 1) & 1) ^ r2b;
    int r0b = (warp & 1) ^ r1b;
    const int Rlo = r0b | (r1b << 1) | (r2b << 2);   // bit3 = 0

    float p_lo = 0.f, p_hi = 0.f, acc9 = 0.f, acc10 = 0.f, acc11 = 0.f;
    #pragma unroll
    for (int r = 0; r < 16; r++) {
        float p = fmaf(a[r].x, a[r].x, a[r].y * a[r].y);
        if (r < 8) p_lo += p; else p_hi += p;
        acc9  += (r & 1) ? -p : p;
        acc10 += (r & 2) ? -p : p;
        int sb = ((r >> 2) ^ (r >> 3) ^ Rlo) & 1;     // v11 sign bit
        acc11 += sb ? -p : p;
    }
    const float ptot = p_lo + p_hi;
    const float dlh  = p_lo - p_hi;

    float acc[NQ];
    #pragma unroll
    for (int q = 0; q < 4; q++)
        acc[q] = ((Rlo >> q) & 1) ? -dlh : dlh;
    #pragma unroll
    for (int q = 4; q < 9; q++)
        acc[q] = ((lane >> (q - 4)) & 1) ? -ptot : ptot;
    acc[9] = acc9; acc[10] = acc10; acc[11] = acc11;

    #pragma unroll
    for (int q = 0; q < NQ; q++) {
        float v = acc[q];
        #pragma unroll
        for (int off = 16; off; off >>= 1)
            v += __shfl_xor_sync(0xffffffffu, v, off);
        acc[q] = v;
    }
    if (lane == 0) {
        #pragma unroll
        for (int q = 0; q < NQ; q++) w_acc[warp][q] = acc[q];
    }
    __syncthreads();
    if (tid < NQ) {
        float v = 0.0f;
        #pragma unroll
        for (int wi = 0; wi < NT / 32; wi++) v += w_acc[wi][tid];
        out[blk * NQ + (NQ - 1 - tid)] = v;
    }
}

extern "C" void kernel_launch(void* const* d_in, const int* in_sizes, int n_in,
                              void* d_out, int out_size) {
    const float* x = (const float*)d_in[0];   // (B, 12) float32
    const float* w = (const float*)d_in[1];   // (2, 12) float32
    float* out = (float*)d_out;               // (B, 12) float32
    int B = in_sizes[0] / NQ;
    qsim_kernel<<<B, NT>>>(x, w, out);
}

// round 5
// speedup vs baseline: 4.6697x; 1.0774x over previous
#include <cuda_runtime.h>

#define NQ 12
#define NT 256
#define NL 2

// Slot index s = warp*512 + lane*16 + r  (bits 0-3 = r, 4-8 = lane, 9-11 = warp)
// Reference convention: qubit j <-> logical bit (11-j) of the state index.
// All RX gates are applied register-locally in one of three frames per layer:
//   frame I  : regs = logical 0-3
//   frame f1 : regs = logical 4-7   (T1 = swap slot bits 0-3 <-> 4-7)
//   frame f2 : regs = logical 8-11  (T2 = swap slot bits 0-3 <-> 8-11)
// The 12-CNOT ring composes into GF(2)-linear map P, folded into T3 (layer 1)
// or the expectation signs (layer 2).

template<int B>
__device__ __forceinline__ void rx_local(float2 (&a)[16], float c, float s) {
    #pragma unroll
    for (int r = 0; r < 16; r++) {
        if (!((r >> B) & 1)) {
            const int r1 = r | (1 << B);
            float x0 = a[r].x, y0 = a[r].y, x1 = a[r1].x, y1 = a[r1].y;
            a[r].x  = fmaf(c, x0,  s * y1);
            a[r].y  = fmaf(c, y0, -s * x1);
            a[r1].x = fmaf(c, x1,  s * y0);
            a[r1].y = fmaf(c, y1, -s * x0);
        }
    }
}

__global__ void __launch_bounds__(NT, 3)
qsim_kernel(const float* __restrict__ x, const float* __restrict__ w,
            float* __restrict__ out) {
    __shared__ float2 sbuf[4096];           // 32 KB transpose buffer
    __shared__ float tc[NL + 1][NQ];        // trig, indexed by logical BIT
    __shared__ float tsn[NL + 1][NQ];
    __shared__ float w_acc[NT / 32][NQ];

    const int tid  = threadIdx.x;
    const int lane = tid & 31;
    const int wp   = tid >> 5;
    const int blk  = blockIdx.x;

    if (tid < NQ) {
        float th = 0.5f * x[blk * NQ + (NQ - 1 - tid)];
        tc[0][tid] = cosf(th);
        tsn[0][tid] = sinf(th);
    } else if (tid < NQ * (NL + 1)) {
        int t = tid - NQ;
        int l = t / NQ, q = t % NQ;
        float th = 0.5f * w[l * NQ + (NQ - 1 - q)];
        tc[l + 1][q] = cosf(th);
        tsn[l + 1][q] = sinf(th);
    }
    __syncthreads();

    float2 a[16];

    // ---- init: product state after input RX layer on |0...0> (frame I) ----
    {
        float mh = 1.0f;
        #pragma unroll
        for (int b = 0; b < 8; b++)
            mh *= ((tid >> b) & 1) ? tsn[0][b + 4] : tc[0][b + 4];
        int pch = __popc(tid);
        #pragma unroll
        for (int r = 0; r < 16; r++) {
            float m = mh;
            #pragma unroll
            for (int b = 0; b < 4; b++)
                m *= ((r >> b) & 1) ? tsn[0][b] : tc[0][b];
            int pc = (pch + __popc(r)) & 3;
            a[r].x = (pc == 0) ? m : (pc == 2) ? -m : 0.0f;
            a[r].y = (pc == 1) ? -m : (pc == 3) ? m : 0.0f;
        }
    }

    bool first = true;
    #pragma unroll 1
    for (int l = 1; l <= NL; l++) {
        // RX logical 0-3 (frame I)
        rx_local<0>(a, tc[l][0], tsn[l][0]);
        rx_local<1>(a, tc[l][1], tsn[l][1]);
        rx_local<2>(a, tc[l][2], tsn[l][2]);
        rx_local<3>(a, tc[l][3], tsn[l][3]);

        // ---- T1: swap slot bits 0-3 <-> 4-7 (swizzle l^r) ----
        if (!first) __syncthreads();
        first = false;
        #pragma unroll
        for (int r = 0; r < 16; r++)
            sbuf[(r << 8) | (wp << 5) | (lane ^ r)] = a[r];
        __syncthreads();
        #pragma unroll
        for (int r = 0; r < 16; r++)
            a[r] = sbuf[((lane & 15) << 8) | (wp << 5) | (lane & 16) | (r ^ (lane & 15))];

        // RX logical 4-7 (frame f1: regs = logical 4-7)
        rx_local<0>(a, tc[l][4], tsn[l][4]);
        rx_local<1>(a, tc[l][5], tsn[l][5]);
        rx_local<2>(a, tc[l][6], tsn[l][6]);
        rx_local<3>(a, tc[l][7], tsn[l][7]);

        // ---- T2: swap slot bits 0-3 <-> 8-11 (swizzle l^((r&1)<<4)) ----
        __syncthreads();
        #pragma unroll
        for (int r = 0; r < 16; r++)
            sbuf[(r << 8) | (wp << 5) | (lane ^ ((r & 1) << 4))] = a[r];
        __syncthreads();
        #pragma unroll
        for (int r = 0; r < 16; r++) {
            int ru = (lane >> 4) | (wp << 1);
            int ad = (ru << 8) | ((r >> 1) << 5) | (lane & 15)
                   | ((((r & 1) ^ (lane >> 4))) << 4);
            a[r] = sbuf[ad];
        }

        // RX logical 8-11 (frame f2: regs = logical 8-11)
        rx_local<0>(a, tc[l][8],  tsn[l][8]);
        rx_local<1>(a, tc[l][9],  tsn[l][9]);
        rx_local<2>(a, tc[l][10], tsn[l][10]);
        rx_local<3>(a, tc[l][11], tsn[l][11]);

        if (l == 1) {
            // ---- T3: return to frame I with ALL 12 CNOTs folded ----
            // dest slot s holds a_pre(P(s)); source slot = f2^{-1}(P(s)).
            __syncthreads();
            #pragma unroll
            for (int r = 0; r < 16; r++)
                sbuf[(r << 8) | (wp << 5) | (lane ^ wp)] = a[r];
            __syncthreads();
            #pragma unroll
            for (int r = 0; r < 16; r++) {
                int s  = (wp << 9) | (lane << 4) | r;
                int P  = ((s ^ (s >> 1)) & 0x3FF)
                       | ((((s >> 10) ^ (s >> 11) ^ s) & 1) << 10)
                       | ((((s >> 11) ^ s) & 1) << 11);
                int ru = P >> 8;
                int wu = (P >> 5) & 7;
                int lu = P & 31;
                a[r] = sbuf[(ru << 8) | (wu << 5) | (lu ^ wu)];
            }
        }
        // l == 2: stay in frame f2 with pending P; folded into expectations.
    }

    // ---- expectations: slot s holds a_fin at logical V = P^{-1}(f2(s)) ----
    // y = f2(s) = (r<<8)|(wp<<5)|lane ; V_k = parity(y_{k..11}), V11 = parity(y_{0..10}).
    // For k=0..7: V_k = gamma_k(lane,wp) ^ parity(r)  -> all fold onto sum D.
    float D = 0.f, E = 0.f, F = 0.f, G = 0.f;
    #pragma unroll
    for (int r = 0; r < 16; r++) {
        float p = fmaf(a[r].x, a[r].x, a[r].y * a[r].y);
        D += (__popc(r)      & 1) ? -p : p;   // parity(r0..r3)
        E += (__popc(r >> 1) & 1) ? -p : p;   // r1^r2^r3
        F += (__popc(r & 12) & 1) ? -p : p;   // r2^r3
        G += (__popc(r & 7)  & 1) ? -p : p;   // r0^r1^r2
    }
    const int pl = __popc(lane) & 1;
    const int pw = __popc(wp) & 1;

    float acc[NQ];
    {
        int g;
        g = pl ^ pw;                          acc[0] = g ? -D : D;
        g = (__popc(lane & 30) & 1) ^ pw;     acc[1] = g ? -D : D;
        g = (__popc(lane & 28) & 1) ^ pw;     acc[2] = g ? -D : D;
        g = (__popc(lane & 24) & 1) ^ pw;     acc[3] = g ? -D : D;
        g = ((lane >> 4) & 1) ^ pw;           acc[4] = g ? -D : D;
        g = pw;                               acc[5] = g ? -D : D;
        g = ((wp >> 1) ^ (wp >> 2)) & 1;      acc[6] = g ? -D : D;
        g = (wp >> 2) & 1;                    acc[7] = g ? -D : D;
        acc[8] = D;
        acc[9] = E;
        acc[10] = F;
        acc[11] = (pl ^ pw) ? -G : G;
    }

    #pragma unroll
    for (int q = 0; q < NQ; q++) {
        float v = acc[q];
        #pragma unroll
        for (int off = 16; off; off >>= 1)
            v += __shfl_xor_sync(0xffffffffu, v, off);
        acc[q] = v;
    }
    if (lane == 0) {
        #pragma unroll
        for (int q = 0; q < NQ; q++) w_acc[wp][q] = acc[q];
    }
    __syncthreads();
    if (tid < NQ) {
        float v = 0.0f;
        #pragma unroll
        for (int wi = 0; wi < NT / 32; wi++) v += w_acc[wi][tid];
        out[blk * NQ + (NQ - 1 - tid)] = v;
    }
}

extern "C" void kernel_launch(void* const* d_in, const int* in_sizes, int n_in,
                              void* d_out, int out_size) {
    const float* x = (const float*)d_in[0];   // (B, 12) float32
    const float* w = (const float*)d_in[1];   // (2, 12) float32
    float* out = (float*)d_out;               // (B, 12) float32
    int B = in_sizes[0] / NQ;
    qsim_kernel<<<B, NT>>>(x, w, out);
}

// round 6
// speedup vs baseline: 4.8275x; 1.0338x over previous
#include <cuda_runtime.h>

#define NQ 12
#define NT 256
#define NL 2

typedef unsigned long long u64;

// ---- packed f32x2 helpers ----
__device__ __forceinline__ u64 pack2(float lo, float hi) {
    u64 v; asm("mov.b64 %0, {%1, %2};" : "=l"(v) : "f"(lo), "f"(hi)); return v;
}
__device__ __forceinline__ void unpack2(u64 v, float &lo, float &hi) {
    asm("mov.b64 {%0, %1}, %2;" : "=f"(lo), "=f"(hi) : "l"(v));
}
__device__ __forceinline__ u64 swap2(u64 v) {
    float lo, hi; unpack2(v, lo, hi); return pack2(hi, lo);
}
__device__ __forceinline__ u64 fma2(u64 a, u64 b, u64 c) {
    u64 d; asm("fma.rn.f32x2 %0, %1, %2, %3;" : "=l"(d) : "l"(a), "l"(b), "l"(c)); return d;
}
__device__ __forceinline__ u64 mul2(u64 a, u64 b) {
    u64 d; asm("mul.rn.f32x2 %0, %1, %2;" : "=l"(d) : "l"(a), "l"(b)); return d;
}

// State: X[j] = (re[j], re[j|8]), Y[j] = (im[j], im[j|8]), j = slot bits 0-2,
// packed half = slot bit 3. Slot s = wp*512 + lane*16 + r.
// Reference convention: qubit j <-> logical bit (11-j).

// RX on register bit B in {0,1,2}: both packed halves use identical coeffs.
template<int B>
__device__ __forceinline__ void rx_low(u64 (&X)[8], u64 (&Y)[8],
                                       u64 c2, u64 s2, u64 sn2) {
    #pragma unroll
    for (int j = 0; j < 8; j++) {
        if (!((j >> B) & 1)) {
            const int j1 = j | (1 << B);
            u64 x0 = X[j], x1 = X[j1], y0 = Y[j], y1 = Y[j1];
            X[j]  = fma2(c2, x0, mul2(s2,  y1));
            X[j1] = fma2(c2, x1, mul2(s2,  y0));
            Y[j]  = fma2(c2, y0, mul2(sn2, x1));
            Y[j1] = fma2(c2, y1, mul2(sn2, x0));
        }
    }
}

// RX on the packed bit (slot bit 3): partner is the swapped half.
__device__ __forceinline__ void rx_b3(u64 (&X)[8], u64 (&Y)[8],
                                      u64 c2, u64 s2, u64 sn2) {
    #pragma unroll
    for (int j = 0; j < 8; j++) {
        u64 sx = swap2(X[j]);
        u64 sy = swap2(Y[j]);
        X[j] = fma2(c2, X[j], mul2(s2,  sy));
        Y[j] = fma2(c2, Y[j], mul2(sn2, sx));
    }
}

__global__ void __launch_bounds__(NT, 3)
qsim_kernel(const float* __restrict__ x, const float* __restrict__ w,
            float* __restrict__ out) {
    __shared__ float2 sbuf[4096];
    __shared__ float tc[NL + 1][NQ];
    __shared__ float tsn[NL + 1][NQ];
    __shared__ float w_acc[NT / 32][NQ];

    const int tid  = threadIdx.x;
    const int lane = tid & 31;
    const int wp   = tid >> 5;
    const int blk  = blockIdx.x;

    if (tid < NQ) {
        float th = 0.5f * x[blk * NQ + (NQ - 1 - tid)];
        tc[0][tid] = cosf(th);
        tsn[0][tid] = sinf(th);
    } else if (tid < NQ * (NL + 1)) {
        int t = tid - NQ;
        int l = t / NQ, q = t % NQ;
        float th = 0.5f * w[l * NQ + (NQ - 1 - q)];
        tc[l + 1][q] = cosf(th);
        tsn[l + 1][q] = sinf(th);
    }
    __syncthreads();

    u64 X[8], Y[8];

    // ---- init: product state after input RX layer on |0...0> ----
    {
        float mh = 1.0f;
        #pragma unroll
        for (int b = 0; b < 8; b++)
            mh *= ((tid >> b) & 1) ? tsn[0][b + 4] : tc[0][b + 4];
        const int pch = __popc(tid);
        const float m3c = tc[0][3], m3s = tsn[0][3];
        #pragma unroll
        for (int j = 0; j < 8; j++) {
            float mj = mh;
            #pragma unroll
            for (int b = 0; b < 3; b++)
                mj *= ((j >> b) & 1) ? tsn[0][b] : tc[0][b];
            float mlo = mj * m3c, mhi = mj * m3s;
            int pc  = (pch + __popc(j)) & 3;
            int pc2 = (pc + 1) & 3;
            float relo = (pc  == 0) ?  mlo : (pc  == 2) ? -mlo : 0.0f;
            float imlo = (pc  == 1) ? -mlo : (pc  == 3) ?  mlo : 0.0f;
            float rehi = (pc2 == 0) ?  mhi : (pc2 == 2) ? -mhi : 0.0f;
            float imhi = (pc2 == 1) ? -mhi : (pc2 == 3) ?  mhi : 0.0f;
            X[j] = pack2(relo, rehi);
            Y[j] = pack2(imlo, imhi);
        }
    }

    bool first = true;
    #pragma unroll 1
    for (int l = 1; l <= NL; l++) {
        // ---- frame I: reg bits 0-3 = logical 0-3 ----
        #pragma unroll
        for (int q = 0; q < 4; q++) {
            float c = tc[l][q], s = tsn[l][q];
            u64 c2 = pack2(c, c), s2 = pack2(s, s), sn2 = pack2(-s, -s);
            if (q == 0) rx_low<0>(X, Y, c2, s2, sn2);
            else if (q == 1) rx_low<1>(X, Y, c2, s2, sn2);
            else if (q == 2) rx_low<2>(X, Y, c2, s2, sn2);
            else rx_b3(X, Y, c2, s2, sn2);
        }

        // ---- T1: swap slot bits 0-3 <-> 4-7 ----
        if (!first) __syncthreads();
        first = false;
        #pragma unroll
        for (int j = 0; j < 8; j++) {
            float xl, xh, yl, yh;
            unpack2(X[j], xl, xh);
            unpack2(Y[j], yl, yh);
            sbuf[(j << 8) | (wp << 5) | (lane ^ j)]             = make_float2(xl, yl);
            sbuf[((j | 8) << 8) | (wp << 5) | (lane ^ (j | 8))] = make_float2(xh, yh);
        }
        __syncthreads();
        #pragma unroll
        for (int j = 0; j < 8; j++) {
            const int base = ((lane & 15) << 8) | (wp << 5) | (lane & 16);
            float2 t0 = sbuf[base | (j ^ (lane & 15))];
            float2 t1 = sbuf[base | ((j | 8) ^ (lane & 15))];
            X[j] = pack2(t0.x, t1.x);
            Y[j] = pack2(t0.y, t1.y);
        }

        // ---- frame f1: reg bits 0-3 = logical 4-7 ----
        #pragma unroll
        for (int q = 0; q < 4; q++) {
            float c = tc[l][q + 4], s = tsn[l][q + 4];
            u64 c2 = pack2(c, c), s2 = pack2(s, s), sn2 = pack2(-s, -s);
            if (q == 0) rx_low<0>(X, Y, c2, s2, sn2);
            else if (q == 1) rx_low<1>(X, Y, c2, s2, sn2);
            else if (q == 2) rx_low<2>(X, Y, c2, s2, sn2);
            else rx_b3(X, Y, c2, s2, sn2);
        }

        // ---- T2: swap slot bits 0-3 <-> 8-11 ----
        __syncthreads();
        #pragma unroll
        for (int j = 0; j < 8; j++) {
            float xl, xh, yl, yh;
            unpack2(X[j], xl, xh);
            unpack2(Y[j], yl, yh);
            sbuf[(j << 8) | (wp << 5) | (lane ^ ((j & 1) << 4))]       = make_float2(xl, yl);
            sbuf[((j | 8) << 8) | (wp << 5) | (lane ^ ((j & 1) << 4))] = make_float2(xh, yh);
        }
        __syncthreads();
        #pragma unroll
        for (int j = 0; j < 8; j++) {
            const int ru = (lane >> 4) | (wp << 1);
            int r0 = j, r1 = j | 8;
            int a0 = (ru << 8) | ((r0 >> 1) << 5) | (lane & 15)
                   | (((r0 & 1) ^ (lane >> 4)) << 4);
            int a1 = (ru << 8) | ((r1 >> 1) << 5) | (lane & 15)
                   | (((r1 & 1) ^ (lane >> 4)) << 4);
            float2 t0 = sbuf[a0];
            float2 t1 = sbuf[a1];
            X[j] = pack2(t0.x, t1.x);
            Y[j] = pack2(t0.y, t1.y);
        }

        // ---- frame f2: reg bits 0-3 = logical 8-11 ----
        #pragma unroll
        for (int q = 0; q < 4; q++) {
            float c = tc[l][q + 8], s = tsn[l][q + 8];
            u64 c2 = pack2(c, c), s2 = pack2(s, s), sn2 = pack2(-s, -s);
            if (q == 0) rx_low<0>(X, Y, c2, s2, sn2);
            else if (q == 1) rx_low<1>(X, Y, c2, s2, sn2);
            else if (q == 2) rx_low<2>(X, Y, c2, s2, sn2);
            else rx_b3(X, Y, c2, s2, sn2);
        }

        if (l == 1) {
            // ---- T3: back to frame I with all 12 CNOTs folded ----
            __syncthreads();
            #pragma unroll
            for (int j = 0; j < 8; j++) {
                float xl, xh, yl, yh;
                unpack2(X[j], xl, xh);
                unpack2(Y[j], yl, yh);
                sbuf[(j << 8) | (wp << 5) | (lane ^ wp)]       = make_float2(xl, yl);
                sbuf[((j | 8) << 8) | (wp << 5) | (lane ^ wp)] = make_float2(xh, yh);
            }
            __syncthreads();
            #pragma unroll
            for (int j = 0; j < 8; j++) {
                float v[2][2];
                #pragma unroll
                for (int h = 0; h < 2; h++) {
                    int r = j | (h << 3);
                    int s  = (wp << 9) | (lane << 4) | r;
                    int P  = ((s ^ (s >> 1)) & 0x3FF)
                           | ((((s >> 10) ^ (s >> 11) ^ s) & 1) << 10)
                           | ((((s >> 11) ^ s) & 1) << 11);
                    int ru = P >> 8;
                    int wu = (P >> 5) & 7;
                    int lu = P & 31;
                    float2 t = sbuf[(ru << 8) | (wu << 5) | (lu ^ wu)];
                    v[h][0] = t.x; v[h][1] = t.y;
                }
                X[j] = pack2(v[0][0], v[1][0]);
                Y[j] = pack2(v[0][1], v[1][1]);
            }
        }
        // l == 2: stay in frame f2 with pending ring perm; folded below.
    }

    // ---- expectations (frame f2 + pending perm folded into signs) ----
    const u64 one2  = pack2(1.0f, 1.0f);
    const u64 mone2 = pack2(-1.0f, -1.0f);
    u64 Dp, Ep, Fp;
    {
        u64 P = fma2(X[0], X[0], mul2(Y[0], Y[0]));
        Dp = P; Ep = P; Fp = P;
    }
    #pragma unroll
    for (int j = 1; j < 8; j++) {
        u64 P = fma2(X[j], X[j], mul2(Y[j], Y[j]));
        Dp = fma2((__popc(j) & 1) ? mone2 : one2, P, Dp);
        Ep = fma2((((j >> 1) ^ (j >> 2)) & 1) ? mone2 : one2, P, Ep);
        Fp = fma2(((j >> 2) & 1) ? mone2 : one2, P, Fp);
    }
    float dlo, dhi, elo, ehi, flo, fhi;
    unpack2(Dp, dlo, dhi);
    unpack2(Ep, elo, ehi);
    unpack2(Fp, flo, fhi);
    const float D = dlo - dhi;   // sign parity(r0..r3)
    const float E = elo - ehi;   // sign r1^r2^r3
    const float F = flo - fhi;   // sign r2^r3
    const float G = dlo + dhi;   // sign r0^r1^r2

    const int pl = __popc(lane) & 1;
    const int pw = __popc(wp) & 1;

    float acc[NQ];
    {
        int g;
        g = pl ^ pw;                          acc[0] = g ? -D : D;
        g = (__popc(lane & 30) & 1) ^ pw;     acc[1] = g ? -D : D;
        g = (__popc(lane & 28) & 1) ^ pw;     acc[2] = g ? -D : D;
        g = (__popc(lane & 24) & 1) ^ pw;     acc[3] = g ? -D : D;
        g = ((lane >> 4) & 1) ^ pw;           acc[4] = g ? -D : D;
        g = pw;                               acc[5] = g ? -D : D;
        g = ((wp >> 1) ^ (wp >> 2)) & 1;      acc[6] = g ? -D : D;
        g = (wp >> 2) & 1;                    acc[7] = g ? -D : D;
        acc[8] = D;
        acc[9] = E;
        acc[10] = F;
        acc[11] = (pl ^ pw) ? -G : G;
    }

    #pragma unroll
    for (int q = 0; q < NQ; q++) {
        float v = acc[q];
        #pragma unroll
        for (int off = 16; off; off >>= 1)
            v += __shfl_xor_sync(0xffffffffu, v, off);
        acc[q] = v;
    }
    if (lane == 0) {
        #pragma unroll
        for (int q = 0; q < NQ; q++) w_acc[wp][q] = acc[q];
    }
    __syncthreads();
    if (tid < NQ) {
        float v = 0.0f;
        #pragma unroll
        for (int wi = 0; wi < NT / 32; wi++) v += w_acc[wi][tid];
        out[blk * NQ + (NQ - 1 - tid)] = v;
    }
}

extern "C" void kernel_launch(void* const* d_in, const int* in_sizes, int n_in,
                              void* d_out, int out_size) {
    const float* x = (const float*)d_in[0];   // (B, 12) float32
    const float* w = (const float*)d_in[1];   // (2, 12) float32
    float* out = (float*)d_out;               // (B, 12) float32
    int B = in_sizes[0] / NQ;
    qsim_kernel<<<B, NT>>>(x, w, out);
}

// round 7
// speedup vs baseline: 5.2205x; 1.0814x over previous
#include <cuda_runtime.h>

#define NQ 12
#define NT 256
#define NL 2

typedef unsigned long long u64;

// ---- packed f32x2 helpers ----
__device__ __forceinline__ u64 pack2(float lo, float hi) {
    u64 v; asm("mov.b64 %0, {%1, %2};" : "=l"(v) : "f"(lo), "f"(hi)); return v;
}
__device__ __forceinline__ void unpack2(u64 v, float &lo, float &hi) {
    asm("mov.b64 {%0, %1}, %2;" : "=f"(lo), "=f"(hi) : "l"(v));
}
__device__ __forceinline__ u64 swap2(u64 v) {
    float lo, hi; unpack2(v, lo, hi); return pack2(hi, lo);
}
__device__ __forceinline__ u64 fma2(u64 a, u64 b, u64 c) {
    u64 d; asm("fma.rn.f32x2 %0, %1, %2, %3;" : "=l"(d) : "l"(a), "l"(b), "l"(c)); return d;
}
__device__ __forceinline__ u64 mul2(u64 a, u64 b) {
    u64 d; asm("mul.rn.f32x2 %0, %1, %2;" : "=l"(d) : "l"(a), "l"(b)); return d;
}
__device__ __forceinline__ u64 add2(u64 a, u64 b) {
    u64 d; asm("add.rn.f32x2 %0, %1, %2;" : "=l"(d) : "l"(a), "l"(b)); return d;
}

// State: X[j] = (re[j], re[j|8]), Y[j] = (im[j], im[j|8]), j = slot bits 0-2,
// packed half = slot bit 3. Slot s = wp*512 + lane*16 + r.
// Reference convention: qubit j <-> logical bit (11-j).

template<int B>
__device__ __forceinline__ void rx_low(u64 (&X)[8], u64 (&Y)[8],
                                       u64 c2, u64 s2, u64 sn2) {
    #pragma unroll
    for (int j = 0; j < 8; j++) {
        if (!((j >> B) & 1)) {
            const int j1 = j | (1 << B);
            u64 x0 = X[j], x1 = X[j1], y0 = Y[j], y1 = Y[j1];
            X[j]  = fma2(c2, x0, mul2(s2,  y1));
            X[j1] = fma2(c2, x1, mul2(s2,  y0));
            Y[j]  = fma2(c2, y0, mul2(sn2, x1));
            Y[j1] = fma2(c2, y1, mul2(sn2, x0));
        }
    }
}

__device__ __forceinline__ void rx_b3(u64 (&X)[8], u64 (&Y)[8],
                                      u64 c2, u64 s2, u64 sn2) {
    #pragma unroll
    for (int j = 0; j < 8; j++) {
        u64 sx = swap2(X[j]);
        u64 sy = swap2(Y[j]);
        X[j] = fma2(c2, X[j], mul2(s2,  sy));
        Y[j] = fma2(c2, Y[j], mul2(sn2, sx));
    }
}

__global__ void __launch_bounds__(NT, 4)
qsim_kernel(const float* __restrict__ x, const float* __restrict__ w,
            float* __restrict__ out) {
    __shared__ float2 sbuf[4096];
    __shared__ float2 trig[NL + 1][NQ];     // (cos, sin), indexed by logical BIT
    __shared__ float w_acc[NT / 32][NQ];

    const int tid  = threadIdx.x;
    const int lane = tid & 31;
    const int wp   = tid >> 5;
    const int blk  = blockIdx.x;

    if (tid < NQ * (NL + 1)) {
        int l = tid / NQ, q = tid % NQ;
        float th = 0.5f * (l == 0 ? x[blk * NQ + (NQ - 1 - q)]
                                  : w[(l - 1) * NQ + (NQ - 1 - q)]);
        trig[l][q] = make_float2(cosf(th), sinf(th));
    }
    __syncthreads();

    u64 X[8], Y[8];

    // ---- init: product state after input RX layer on |0...0> ----
    {
        float mh = 1.0f;
        #pragma unroll
        for (int b = 0; b < 8; b++) {
            float2 t = trig[0][b + 4];
            mh *= ((tid >> b) & 1) ? t.y : t.x;
        }
        const int pch = __popc(tid);
        const float2 t3 = trig[0][3];
        #pragma unroll
        for (int j = 0; j < 8; j++) {
            float mj = mh;
            #pragma unroll
            for (int b = 0; b < 3; b++) {
                float2 t = trig[0][b];
                mj *= ((j >> b) & 1) ? t.y : t.x;
            }
            float mlo = mj * t3.x, mhi = mj * t3.y;
            int pc  = (pch + __popc(j)) & 3;
            int pc2 = (pc + 1) & 3;
            float relo = (pc  == 0) ?  mlo : (pc  == 2) ? -mlo : 0.0f;
            float imlo = (pc  == 1) ? -mlo : (pc  == 3) ?  mlo : 0.0f;
            float rehi = (pc2 == 0) ?  mhi : (pc2 == 2) ? -mhi : 0.0f;
            float imhi = (pc2 == 1) ? -mhi : (pc2 == 3) ?  mhi : 0.0f;
            X[j] = pack2(relo, rehi);
            Y[j] = pack2(imlo, imhi);
        }
    }

    bool first = true;
    #pragma unroll 1
    for (int l = 1; l <= NL; l++) {
        // ---- frame I: reg bits 0-3 = logical 0-3 ----
        #pragma unroll
        for (int q = 0; q < 4; q++) {
            float2 t = trig[l][q];
            u64 c2 = pack2(t.x, t.x), s2 = pack2(t.y, t.y), sn2 = pack2(-t.y, -t.y);
            if (q == 0) rx_low<0>(X, Y, c2, s2, sn2);
            else if (q == 1) rx_low<1>(X, Y, c2, s2, sn2);
            else if (q == 2) rx_low<2>(X, Y, c2, s2, sn2);
            else rx_b3(X, Y, c2, s2, sn2);
        }

        // ---- T1: swap slot bits 0-3 <-> 4-7 ----
        if (!first) __syncthreads();
        first = false;
        #pragma unroll
        for (int j = 0; j < 8; j++) {
            float xl, xh, yl, yh;
            unpack2(X[j], xl, xh);
            unpack2(Y[j], yl, yh);
            sbuf[(j << 8) | (wp << 5) | (lane ^ j)]             = make_float2(xl, yl);
            sbuf[((j | 8) << 8) | (wp << 5) | (lane ^ (j | 8))] = make_float2(xh, yh);
        }
        __syncthreads();
        #pragma unroll
        for (int j = 0; j < 8; j++) {
            const int base = ((lane & 15) << 8) | (wp << 5) | (lane & 16);
            float2 t0 = sbuf[base | (j ^ (lane & 15))];
            float2 t1 = sbuf[base | ((j | 8) ^ (lane & 15))];
            X[j] = pack2(t0.x, t1.x);
            Y[j] = pack2(t0.y, t1.y);
        }

        // ---- frame f1: reg bits 0-3 = logical 4-7 ----
        #pragma unroll
        for (int q = 0; q < 4; q++) {
            float2 t = trig[l][q + 4];
            u64 c2 = pack2(t.x, t.x), s2 = pack2(t.y, t.y), sn2 = pack2(-t.y, -t.y);
            if (q == 0) rx_low<0>(X, Y, c2, s2, sn2);
            else if (q == 1) rx_low<1>(X, Y, c2, s2, sn2);
            else if (q == 2) rx_low<2>(X, Y, c2, s2, sn2);
            else rx_b3(X, Y, c2, s2, sn2);
        }

        // ---- T2: swap slot bits 0-3 <-> 8-11 ----
        __syncthreads();
        #pragma unroll
        for (int j = 0; j < 8; j++) {
            float xl, xh, yl, yh;
            unpack2(X[j], xl, xh);
            unpack2(Y[j], yl, yh);
            sbuf[(j << 8) | (wp << 5) | (lane ^ ((j & 1) << 4))]       = make_float2(xl, yl);
            sbuf[((j | 8) << 8) | (wp << 5) | (lane ^ ((j & 1) << 4))] = make_float2(xh, yh);
        }
        __syncthreads();
        #pragma unroll
        for (int j = 0; j < 8; j++) {
            const int ru = (lane >> 4) | (wp << 1);
            int r0 = j, r1 = j | 8;
            int a0 = (ru << 8) | ((r0 >> 1) << 5) | (lane & 15)
                   | (((r0 & 1) ^ (lane >> 4)) << 4);
            int a1 = (ru << 8) | ((r1 >> 1) << 5) | (lane & 15)
                   | (((r1 & 1) ^ (lane >> 4)) << 4);
            float2 t0 = sbuf[a0];
            float2 t1 = sbuf[a1];
            X[j] = pack2(t0.x, t1.x);
            Y[j] = pack2(t0.y, t1.y);
        }

        // ---- frame f2: reg bits 0-3 = logical 8-11 ----
        #pragma unroll
        for (int q = 0; q < 4; q++) {
            float2 t = trig[l][q + 8];
            u64 c2 = pack2(t.x, t.x), s2 = pack2(t.y, t.y), sn2 = pack2(-t.y, -t.y);
            if (q == 0) rx_low<0>(X, Y, c2, s2, sn2);
            else if (q == 1) rx_low<1>(X, Y, c2, s2, sn2);
            else if (q == 2) rx_low<2>(X, Y, c2, s2, sn2);
            else rx_b3(X, Y, c2, s2, sn2);
        }

        if (l == 1) {
            // ---- T3: back to frame I with all 12 CNOTs folded ----
            __syncthreads();
            #pragma unroll
            for (int j = 0; j < 8; j++) {
                float xl, xh, yl, yh;
                unpack2(X[j], xl, xh);
                unpack2(Y[j], yl, yh);
                sbuf[(j << 8) | (wp << 5) | (lane ^ wp)]       = make_float2(xl, yl);
                sbuf[((j | 8) << 8) | (wp << 5) | (lane ^ wp)] = make_float2(xh, yh);
            }
            __syncthreads();
            #pragma unroll
            for (int j = 0; j < 8; j++) {
                float v[2][2];
                #pragma unroll
                for (int h = 0; h < 2; h++) {
                    int r = j | (h << 3);
                    int s  = (wp << 9) | (lane << 4) | r;
                    int P  = ((s ^ (s >> 1)) & 0x3FF)
                           | ((((s >> 10) ^ (s >> 11) ^ s) & 1) << 10)
                           | ((((s >> 11) ^ s) & 1) << 11);
                    int ru = P >> 8;
                    int wu = (P >> 5) & 7;
                    int lu = P & 31;
                    float2 t = sbuf[(ru << 8) | (wu << 5) | (lu ^ wu)];
                    v[h][0] = t.x; v[h][1] = t.y;
                }
                X[j] = pack2(v[0][0], v[1][0]);
                Y[j] = pack2(v[0][1], v[1][1]);
            }
        }
        // l == 2: stay in frame f2 with pending ring perm; folded below.
    }

    // ---- expectations (frame f2 + pending perm folded into signs) ----
    const u64 one2  = pack2(1.0f, 1.0f);
    const u64 mone2 = pack2(-1.0f, -1.0f);
    u64 Dp, Ep, Fp;
    {
        u64 P = fma2(X[0], X[0], mul2(Y[0], Y[0]));
        Dp = P; Ep = P; Fp = P;
    }
    #pragma unroll
    for (int j = 1; j < 8; j++) {
        u64 P = fma2(X[j], X[j], mul2(Y[j], Y[j]));
        Dp = fma2((__popc(j) & 1) ? mone2 : one2, P, Dp);
        Ep = fma2((((j >> 1) ^ (j >> 2)) & 1) ? mone2 : one2, P, Ep);
        Fp = fma2(((j >> 2) & 1) ? mone2 : one2, P, Fp);
    }
    // D: sign parity(r0..r3); G: sign r0^r1^r2; E: r1^r2^r3; F: r2^r3
    u64 DG, EF;
    {
        float dlo, dhi, elo, ehi, flo, fhi;
        unpack2(Dp, dlo, dhi);
        unpack2(Ep, elo, ehi);
        unpack2(Fp, flo, fhi);
        DG = pack2(dlo - dhi, dlo + dhi);
        EF = pack2(elo - ehi, flo - fhi);
    }

    // Packed Walsh-Hadamard over the 5 lane bits on (D,G);
    // plain packed allreduce on (E,F). After WHT, lane m holds
    // bin m: sum_l (-1)^{<m,l>} D_l (and G_l).
    #pragma unroll
    for (int st = 0; st < 5; st++) {
        const int m = 1 << st;
        u64 tD = __shfl_xor_sync(0xffffffffu, DG, m);
        u64 tE = __shfl_xor_sync(0xffffffffu, EF, m);
        DG = fma2((lane & m) ? mone2 : one2, DG, tD);
        EF = add2(EF, tE);
    }

    {
        float cD, cG, cE, cF;
        unpack2(DG, cD, cG);
        unpack2(EF, cE, cF);
        const int pw = __popc(wp) & 1;
        const float sD = pw ? -cD : cD;
        if (lane == 31) {
            w_acc[wp][0]  = sD;
            w_acc[wp][11] = pw ? -cG : cG;
        } else if (lane == 30) w_acc[wp][1] = sD;
        else if (lane == 28)   w_acc[wp][2] = sD;
        else if (lane == 24)   w_acc[wp][3] = sD;
        else if (lane == 16)   w_acc[wp][4] = sD;
        else if (lane == 0) {
            w_acc[wp][5] = sD;
            w_acc[wp][6] = (((wp >> 1) ^ (wp >> 2)) & 1) ? -cD : cD;
            w_acc[wp][7] = ((wp >> 2) & 1) ? -cD : cD;
            w_acc[wp][8] = cD;
            w_acc[wp][9] = cE;
            w_acc[wp][10] = cF;
        }
    }
    __syncthreads();
    if (tid < NQ) {
        float v = 0.0f;
        #pragma unroll
        for (int wi = 0; wi < NT / 32; wi++) v += w_acc[wi][tid];
        out[blk * NQ + (NQ - 1 - tid)] = v;
    }
}

extern "C" void kernel_launch(void* const* d_in, const int* in_sizes, int n_in,
                              void* d_out, int out_size) {
    const float* x = (const float*)d_in[0];   // (B, 12) float32
    const float* w = (const float*)d_in[1];   // (2, 12) float32
    float* out = (float*)d_out;               // (B, 12) float32
    int B = in_sizes[0] / NQ;
    qsim_kernel<<<B, NT>>>(x, w, out);
}